// round 3
// baseline (speedup 1.0000x reference)
#include <cuda_runtime.h>
#include <math_constants.h>

// Problem constants (fixed shapes from reference)
#define HFEAT 200
#define WFEAT 320
#define HWFEAT (HFEAT * WFEAT)      // 64000 pixels
#define CFEAT 256
#define NROI 128
#define MSZ 14
#define NBIN (MSZ * MSZ)            // 196
#define NPTS (NROI * NBIN * 4)      // 100352 sample points
#define NCB 8                       // channel blocks
#define CPB 32                      // channels per block

// Scratch (static device arrays — no allocation)
__device__ __align__(16) float g_Mb[HWFEAT * NCB];   // [pix][cb] per-pixel block maxes (2 MB)
__device__ __align__(16) float g_best[NBIN];         // per-bin running exact max

// ---------------------------------------------------------------------------
// float atomicMax via signed/unsigned int atomics (monotone non-decreasing,
// order-independent => deterministic final value)
// ---------------------------------------------------------------------------
__device__ __forceinline__ void atomicMaxFloat(float* addr, float val) {
    if (val >= 0.0f) {
        atomicMax((int*)addr, __float_as_int(val));
    } else {
        atomicMin((unsigned int*)addr, __float_as_uint(val));
    }
}

// ---------------------------------------------------------------------------
// Init per-bin best to -inf (must run every launch: graph replays reuse state)
// ---------------------------------------------------------------------------
__global__ void k_init() {
    int i = blockIdx.x * blockDim.x + threadIdx.x;
    if (i < NBIN) g_best[i] = -CUDART_INF_F;
}

// ---------------------------------------------------------------------------
// Pass 1: per-pixel channel-block maxes. One thread per pixel, 256 strided
// loads (coalesced across lanes), fully unrolled for MLP. Streams 65.5 MB.
// ---------------------------------------------------------------------------
__global__ void k_colmax(const float* __restrict__ f) {
    int p = blockIdx.x * blockDim.x + threadIdx.x;
    if (p >= HWFEAT) return;
    float mb[NCB];
#pragma unroll
    for (int cb = 0; cb < NCB; cb++) {
        const float* fp = f + (size_t)(cb * CPB) * HWFEAT + p;
        float m = -CUDART_INF_F;
#pragma unroll
        for (int j = 0; j < CPB; j++) {
            m = fmaxf(m, __ldg(fp + (size_t)j * HWFEAT));
        }
        mb[cb] = m;
    }
    float4* dst = reinterpret_cast<float4*>(&g_Mb[(size_t)p * NCB]);
    dst[0] = make_float4(mb[0], mb[1], mb[2], mb[3]);
    dst[1] = make_float4(mb[4], mb[5], mb[6], mb[7]);
}

// ---------------------------------------------------------------------------
// Point pass: one warp per sample point.
//   - decode (r, m, n, sub) from linear pid (r-major)
//   - compute bilinear coords/weights EXACTLY as the reference (clamp corner
//     indices first, weights from clamped corners)
//   - 8 lanes screen the 8 channel blocks: upper bound = bilinear interp of
//     per-pixel block maxes (valid since weights are a convex combination;
//     if any weight is out of [0,1] — clamp triggered — force evaluation)
//   - only blocks whose bound exceeds the current bin best get the exact
//     32-channel evaluation; warp-reduce; atomicMaxFloat into g_best.
// Safe pruning: g_best holds only exact values, so skipping ub<=best points
// can never change the final (exact, deterministic) max.
// ---------------------------------------------------------------------------
__global__ void k_points(const float* __restrict__ f,
                         const float* __restrict__ rois,
                         int base, int count) {
    int w = blockIdx.x * (blockDim.x >> 5) + (threadIdx.x >> 5);
    if (w >= count) return;                 // warp-uniform
    int pid = base + w;
    int lane = threadIdx.x & 31;

    int s = pid & 3;
    int q = pid >> 2;
    int n = q % MSZ; q /= MSZ;
    int m = q % MSZ;
    int r = q / MSZ;

    float r0 = __ldg(&rois[r * 4 + 0]);
    float r1 = __ldg(&rois[r * 4 + 1]);
    float r2 = __ldg(&rois[r * 4 + 2]);
    float r3 = __ldg(&rois[r * 4 + 3]);
    float sh = (r2 - r0) / 14.0f;
    float sw = (r3 - r1) / 14.0f;

    float fy = (s >> 1) ? (2.0f / 3.0f) : (1.0f / 3.0f);
    float fx = (s & 1)  ? (2.0f / 3.0f) : (1.0f / 3.0f);

    float y = (r0 + sh * (float)m) + sh * fy;
    float x = (r1 + sw * (float)n) + sw * fx;

    int yf = (int)floorf(y);
    int xf = (int)floorf(x);
    int y1c = min(max(yf, 0), HFEAT - 1);
    int y2c = min(max(yf + 1, 0), HFEAT - 1);
    int x1c = min(max(xf, 0), WFEAT - 1);
    int x2c = min(max(xf + 1, 0), WFEAT - 1);

    float wy_lo = y - (float)y1c;
    float wy_hi = (float)y2c - y;
    float wx_lo = x - (float)x1c;
    float wx_hi = (float)x2c - x;

    // convexity guard (never triggers with these inputs, but keeps pruning safe)
    bool wok = (wy_lo >= 0.0f) && (wy_lo <= 1.0f) && (wy_hi >= 0.0f) && (wy_hi <= 1.0f) &&
               (wx_lo >= 0.0f) && (wx_lo <= 1.0f) && (wx_hi >= 0.0f) && (wx_hi <= 1.0f);

    int o11 = y1c * WFEAT + x1c;
    int o12 = y1c * WFEAT + x2c;
    int o21 = y2c * WFEAT + x1c;
    int o22 = y2c * WFEAT + x2c;

    int bin = m * MSZ + n;
    float best = __ldcg(&g_best[bin]);   // stale reads only weaken pruning, never wrong

    bool need = false;
    if (lane < NCB) {
        float m11 = __ldg(&g_Mb[(size_t)o11 * NCB + lane]);
        float m12 = __ldg(&g_Mb[(size_t)o12 * NCB + lane]);
        float m21 = __ldg(&g_Mb[(size_t)o21 * NCB + lane]);
        float m22 = __ldg(&g_Mb[(size_t)o22 * NCB + lane]);
        float ub = wy_hi * (wx_hi * m11 + wx_lo * m12) +
                   wy_lo * (wx_hi * m21 + wx_lo * m22);
        need = (!wok) || (ub > best);
    }
    unsigned mask = __ballot_sync(0xffffffffu, need);
    if (!mask) return;

    float vmax = -CUDART_INF_F;
    while (mask) {
        int cb = __ffs(mask) - 1;
        mask &= mask - 1;
        const float* fc = f + (size_t)(cb * CPB + lane) * HWFEAT;
        float a = __ldg(fc + o11);
        float b = __ldg(fc + o12);
        float c = __ldg(fc + o21);
        float d = __ldg(fc + o22);
        float v = wy_hi * (wx_hi * a + wx_lo * b) +
                  wy_lo * (wx_hi * c + wx_lo * d);
        vmax = fmaxf(vmax, v);
    }
#pragma unroll
    for (int o = 16; o; o >>= 1)
        vmax = fmaxf(vmax, __shfl_xor_sync(0xffffffffu, vmax, o));
    if (lane == 0) atomicMaxFloat(&g_best[bin], vmax);
}

// ---------------------------------------------------------------------------
// Broadcast g_best[14*14] to out[R, C, 14, 14] with float4 stores.
// 196 % 4 == 0, so each float4 stays inside one (r,c) tile and mn % 4 == 0.
// ---------------------------------------------------------------------------
__global__ void k_bcast(float4* __restrict__ out, int n4) {
    int i = blockIdx.x * blockDim.x + threadIdx.x;
    if (i >= n4) return;
    int mn = (i * 4) % NBIN;           // multiple of 4
    const float4* b4 = reinterpret_cast<const float4*>(g_best);
    out[i] = __ldg(&b4[mn >> 2]);
}

// ---------------------------------------------------------------------------
extern "C" void kernel_launch(void* const* d_in, const int* in_sizes, int n_in,
                              void* d_out, int out_size) {
    const float* feature = (const float*)d_in[0];   // [1,256,200,320] f32
    const float* rois    = (const float*)d_in[1];   // [128,4] f32
    float* out           = (float*)d_out;           // [128,256,14,14] f32

    k_init<<<1, 256>>>();
    k_colmax<<<(HWFEAT + 255) / 256, 256>>>(feature);

    // Seed exact bests (roi 0, then rois 1-3) before the screened main pass.
    const int WPB = 8;                  // warps (points) per block
    k_points<<<784 / WPB, WPB * 32>>>(feature, rois, 0, 784);          // r = 0
    k_points<<<2352 / WPB, WPB * 32>>>(feature, rois, 784, 2352);      // r = 1..3
    k_points<<<(NPTS - 3136) / WPB, WPB * 32>>>(feature, rois, 3136, NPTS - 3136);

    int n4 = out_size / 4;              // 6422528 / 4 = 1605632
    k_bcast<<<(n4 + 255) / 256, 256>>>((float4*)out, n4);
}

// round 5
// speedup vs baseline: 1.0251x; 1.0251x over previous
#include <cuda_runtime.h>
#include <math_constants.h>

#define HFEAT 200
#define WFEAT 320
#define HWFEAT (HFEAT * WFEAT)      // 64000 pixels
#define HW4 (HWFEAT / 4)            // 16000 pixel-quads
#define CFEAT 256
#define NROI 128
#define MSZ 14
#define NBIN (MSZ * MSZ)            // 196
#define NCB 8                       // channel blocks
#define CPB 32                      // channels per block
#define NCAND (NROI * 4)            // 512 candidate points per bin

// Scratch (static device arrays — no allocation)
__device__ __align__(16) float g_Mb[HWFEAT * NCB];   // [pix][cb] per-pixel block maxes (2 MB)
__device__ __align__(16) float g_best[NBIN];         // per-bin running exact max

// ---------------------------------------------------------------------------
// float atomicMax via int atomics (monotone, order-independent => deterministic)
// ---------------------------------------------------------------------------
__device__ __forceinline__ void atomicMaxFloat(float* addr, float val) {
    if (val >= 0.0f) {
        atomicMax((int*)addr, __float_as_int(val));
    } else {
        atomicMin((unsigned int*)addr, __float_as_uint(val));
    }
}

// ---------------------------------------------------------------------------
// Pass 1: per-pixel channel-block maxes, float4-wide.
// grid = (63, 8): blockIdx.y = channel block, blockIdx.x covers pixel-quads.
// Warp loads 512B contiguous per instruction; 32-deep unroll for MLP.
// Also initializes g_best (runs before any consumer by stream order).
// ---------------------------------------------------------------------------
__global__ void __launch_bounds__(256) k_colmax(const float4* __restrict__ f4) {
    if (blockIdx.x == 0 && blockIdx.y == 0 && threadIdx.x < NBIN)
        g_best[threadIdx.x] = -CUDART_INF_F;

    int pg = blockIdx.x * 256 + threadIdx.x;     // pixel quad
    if (pg >= HW4) return;
    int cb = blockIdx.y;

    const float4* p = f4 + (size_t)(cb * CPB) * HW4 + pg;
    float4 m = make_float4(-CUDART_INF_F, -CUDART_INF_F, -CUDART_INF_F, -CUDART_INF_F);
#pragma unroll
    for (int j = 0; j < CPB; j++) {
        float4 v = __ldg(p + (size_t)j * HW4);
        m.x = fmaxf(m.x, v.x); m.y = fmaxf(m.y, v.y);
        m.z = fmaxf(m.z, v.z); m.w = fmaxf(m.w, v.w);
    }
    int px = pg * 4;
    g_Mb[(size_t)(px + 0) * NCB + cb] = m.x;
    g_Mb[(size_t)(px + 1) * NCB + cb] = m.y;
    g_Mb[(size_t)(px + 2) * NCB + cb] = m.z;
    g_Mb[(size_t)(px + 3) * NCB + cb] = m.w;
}

// ---------------------------------------------------------------------------
// Single point pass: one warp per (bin, candidate). Grid is bin-major
// (x = bin, launched fastest), so wave 1 seeds EVERY bin with the first ~6
// rois at full chip parallelism; later waves see tight bests and prune.
//
// Screen: 8 lanes bound the 8 channel blocks via bilinear interp of per-pixel
// block maxes (convex combination => valid upper bound; clamp case forces
// evaluation). Only blocks whose bound beats the current exact best are
// evaluated (32 channels, 4 corner loads, warp max, atomicMaxFloat).
// Pruning only ever skips provably-dominated work => exact, deterministic.
// ---------------------------------------------------------------------------
__global__ void __launch_bounds__(256) k_points(const float* __restrict__ f,
                                                const float* __restrict__ rois) {
    int bin  = blockIdx.x;                       // 0..195
    int cand = blockIdx.y * 8 + (threadIdx.x >> 5); // 0..511
    int lane = threadIdx.x & 31;

    int r = cand >> 2;
    int s = cand & 3;
    int m = bin / MSZ;
    int n = bin - m * MSZ;

    float r0 = __ldg(&rois[r * 4 + 0]);
    float r1 = __ldg(&rois[r * 4 + 1]);
    float r2 = __ldg(&rois[r * 4 + 2]);
    float r3 = __ldg(&rois[r * 4 + 3]);
    float sh = (r2 - r0) / 14.0f;
    float sw = (r3 - r1) / 14.0f;

    float fy = (s >> 1) ? (2.0f / 3.0f) : (1.0f / 3.0f);
    float fx = (s & 1)  ? (2.0f / 3.0f) : (1.0f / 3.0f);

    float y = (r0 + sh * (float)m) + sh * fy;
    float x = (r1 + sw * (float)n) + sw * fx;

    int yf = (int)floorf(y);
    int xf = (int)floorf(x);
    int y1c = min(max(yf, 0), HFEAT - 1);
    int y2c = min(max(yf + 1, 0), HFEAT - 1);
    int x1c = min(max(xf, 0), WFEAT - 1);
    int x2c = min(max(xf + 1, 0), WFEAT - 1);

    float wy_lo = y - (float)y1c;
    float wy_hi = (float)y2c - y;
    float wx_lo = x - (float)x1c;
    float wx_hi = (float)x2c - x;

    // convexity guard (clamp never triggers on these inputs; keeps pruning safe)
    bool wok = (wy_lo >= 0.0f) && (wy_lo <= 1.0f) && (wy_hi >= 0.0f) && (wy_hi <= 1.0f) &&
               (wx_lo >= 0.0f) && (wx_lo <= 1.0f) && (wx_hi >= 0.0f) && (wx_hi <= 1.0f);

    int o11 = y1c * WFEAT + x1c;
    int o12 = y1c * WFEAT + x2c;
    int o21 = y2c * WFEAT + x1c;
    int o22 = y2c * WFEAT + x2c;

    float best = __ldcg(&g_best[bin]);   // stale reads only weaken pruning, never wrong

    bool need = false;
    if (lane < NCB) {
        float m11 = __ldg(&g_Mb[(size_t)o11 * NCB + lane]);
        float m12 = __ldg(&g_Mb[(size_t)o12 * NCB + lane]);
        float m21 = __ldg(&g_Mb[(size_t)o21 * NCB + lane]);
        float m22 = __ldg(&g_Mb[(size_t)o22 * NCB + lane]);
        float ub = wy_hi * (wx_hi * m11 + wx_lo * m12) +
                   wy_lo * (wx_hi * m21 + wx_lo * m22);
        need = (!wok) || (ub > best);
    }
    unsigned mask = __ballot_sync(0xffffffffu, need);
    if (!mask) return;

    float vmax = -CUDART_INF_F;
    while (mask) {
        int cb = __ffs(mask) - 1;
        mask &= mask - 1;
        const float* fc = f + (size_t)(cb * CPB + lane) * HWFEAT;
        float a = __ldg(fc + o11);
        float b = __ldg(fc + o12);
        float c = __ldg(fc + o21);
        float d = __ldg(fc + o22);
        float v = wy_hi * (wx_hi * a + wx_lo * b) +
                  wy_lo * (wx_hi * c + wx_lo * d);
        vmax = fmaxf(vmax, v);
    }
#pragma unroll
    for (int o = 16; o; o >>= 1)
        vmax = fmaxf(vmax, __shfl_xor_sync(0xffffffffu, vmax, o));
    if (lane == 0) atomicMaxFloat(&g_best[bin], vmax);
}

// ---------------------------------------------------------------------------
// Broadcast g_best[196] to out[R, C, 14, 14] with float4 stores.
// 196 % 4 == 0 so each float4 stays inside one (r,c) tile. g_best staged in
// smem so the store stream has no global-load dependency.
// ---------------------------------------------------------------------------
__global__ void __launch_bounds__(256) k_bcast(float4* __restrict__ out, int n4) {
    __shared__ float4 sb[NBIN / 4];
    if (threadIdx.x < NBIN / 4)
        sb[threadIdx.x] = reinterpret_cast<const float4*>(g_best)[threadIdx.x];
    __syncthreads();
    int i = blockIdx.x * 256 + threadIdx.x;
    if (i >= n4) return;
    out[i] = sb[i % (NBIN / 4)];
}

// ---------------------------------------------------------------------------
extern "C" void kernel_launch(void* const* d_in, const int* in_sizes, int n_in,
                              void* d_out, int out_size) {
    const float* feature = (const float*)d_in[0];   // [1,256,200,320] f32
    const float* rois    = (const float*)d_in[1];   // [128,4] f32
    float* out           = (float*)d_out;           // [128,256,14,14] f32

    // Pass 1: per-pixel block maxes (+ g_best init)
    dim3 g1((HW4 + 255) / 256, NCB);
    k_colmax<<<g1, 256>>>((const float4*)feature);

    // Single screened point pass over all (bin, candidate) pairs.
    dim3 g2(NBIN, NCAND / 8);
    k_points<<<g2, 256>>>(feature, rois);

    // Broadcast result
    int n4 = out_size / 4;              // 6422528 / 4 = 1605632
    k_bcast<<<(n4 + 255) / 256, 256>>>((float4*)out, n4);
}

// round 7
// speedup vs baseline: 2.1624x; 2.1094x over previous
#include <cuda_runtime.h>
#include <math_constants.h>

#define HFEAT 200
#define WFEAT 320
#define HWFEAT (HFEAT * WFEAT)      // 64000 pixels
#define HW4 (HWFEAT / 4)            // 16000 pixel-quads
#define CFEAT 256
#define NROI 128
#define MSZ 14
#define NBIN (MSZ * MSZ)            // 196
#define NCB 16                      // channel blocks (16 channels each)
#define CPB 16                      // channels per block
#define NCAND (NROI * 4)            // 512 candidate points per bin
#define NSEED 8                     // rois used for seeding

// Scratch (static device arrays — no allocation)
__device__ __align__(16) float g_Mb[HWFEAT * NCB];   // [pix][cb] per-pixel 16-ch maxes (4 MB)
__device__ __align__(16) float g_best[NBIN];         // per-bin running exact max

// ---------------------------------------------------------------------------
__device__ __forceinline__ void atomicMaxFloat(float* addr, float val) {
    if (val >= 0.0f) {
        atomicMax((int*)addr, __float_as_int(val));
    } else {
        atomicMin((unsigned int*)addr, __float_as_uint(val));
    }
}

// ---------------------------------------------------------------------------
// Shared geometry: replicate the reference bilinear setup exactly
// (corner indices clamped FIRST, weights computed from clamped corners).
// ---------------------------------------------------------------------------
struct Geom {
    int o11, o12, o21, o22;
    float wy_lo, wy_hi, wx_lo, wx_hi;
    bool wok;   // weights form a convex combination (clamp did not trigger)
};

__device__ __forceinline__ Geom make_geom(const float* __restrict__ rois,
                                          int r, int s, int m, int n) {
    float r0 = __ldg(&rois[r * 4 + 0]);
    float r1 = __ldg(&rois[r * 4 + 1]);
    float r2 = __ldg(&rois[r * 4 + 2]);
    float r3 = __ldg(&rois[r * 4 + 3]);
    float sh = (r2 - r0) / 14.0f;
    float sw = (r3 - r1) / 14.0f;
    float fy = (s >> 1) ? (2.0f / 3.0f) : (1.0f / 3.0f);
    float fx = (s & 1)  ? (2.0f / 3.0f) : (1.0f / 3.0f);
    float y = (r0 + sh * (float)m) + sh * fy;
    float x = (r1 + sw * (float)n) + sw * fx;

    int yf = (int)floorf(y);
    int xf = (int)floorf(x);
    int y1c = min(max(yf, 0), HFEAT - 1);
    int y2c = min(max(yf + 1, 0), HFEAT - 1);
    int x1c = min(max(xf, 0), WFEAT - 1);
    int x2c = min(max(xf + 1, 0), WFEAT - 1);

    Geom g;
    g.wy_lo = y - (float)y1c;
    g.wy_hi = (float)y2c - y;
    g.wx_lo = x - (float)x1c;
    g.wx_hi = (float)x2c - x;
    g.wok = (g.wy_lo >= 0.0f) && (g.wy_lo <= 1.0f) && (g.wy_hi >= 0.0f) && (g.wy_hi <= 1.0f) &&
            (g.wx_lo >= 0.0f) && (g.wx_lo <= 1.0f) && (g.wx_hi >= 0.0f) && (g.wx_hi <= 1.0f);
    g.o11 = y1c * WFEAT + x1c;
    g.o12 = y1c * WFEAT + x2c;
    g.o21 = y2c * WFEAT + x1c;
    g.o22 = y2c * WFEAT + x2c;
    return g;
}

__device__ __forceinline__ float bilin(const float* __restrict__ base, const Geom& g) {
    float a = __ldg(base + g.o11);
    float b = __ldg(base + g.o12);
    float c = __ldg(base + g.o21);
    float d = __ldg(base + g.o22);
    return g.wy_hi * (g.wx_hi * a + g.wx_lo * b) +
           g.wy_lo * (g.wx_hi * c + g.wx_lo * d);
}

// ---------------------------------------------------------------------------
// Pass 1: per-pixel 16-channel-block maxes.
// grid = 1000 blocks; block = 256 threads = 16 cb  x 16 pixel-quads.
// Loads: per (cb,j) each 16-thread group reads 256B contiguous float4s.
// Stores: block-local smem transpose -> one coalesced 4KB float4 burst into
// g_Mb[pix][16]. Also initializes g_best (block 0).
// ---------------------------------------------------------------------------
__global__ void __launch_bounds__(256) k_colmax(const float4* __restrict__ f4) {
    __shared__ float s[64][NCB + 1];    // +1 pad: kill store bank conflicts

    if (blockIdx.x == 0 && threadIdx.x < NBIN)
        g_best[threadIdx.x] = -CUDART_INF_F;

    int qi = threadIdx.x & 15;          // quad within block (0..15)
    int cb = threadIdx.x >> 4;          // channel block (0..15)
    int pg = blockIdx.x * 16 + qi;      // global pixel quad (0..15999)

    const float4* p = f4 + (size_t)(cb * CPB) * HW4 + pg;
    float4 m = make_float4(-CUDART_INF_F, -CUDART_INF_F, -CUDART_INF_F, -CUDART_INF_F);
#pragma unroll
    for (int j = 0; j < CPB; j++) {
        float4 v = __ldg(p + (size_t)j * HW4);
        m.x = fmaxf(m.x, v.x); m.y = fmaxf(m.y, v.y);
        m.z = fmaxf(m.z, v.z); m.w = fmaxf(m.w, v.w);
    }
    int lpx = qi * 4;                   // local pixel 0..63
    s[lpx + 0][cb] = m.x;
    s[lpx + 1][cb] = m.y;
    s[lpx + 2][cb] = m.z;
    s[lpx + 3][cb] = m.w;
    __syncthreads();

    // write 64 px * 16 cb = 256 float4, one per thread, coalesced
    int px  = threadIdx.x >> 2;         // 0..63
    int cb0 = (threadIdx.x & 3) * 4;    // 0,4,8,12
    float4 o = make_float4(s[px][cb0], s[px][cb0 + 1], s[px][cb0 + 2], s[px][cb0 + 3]);
    float4* dst = reinterpret_cast<float4*>(g_Mb + ((size_t)blockIdx.x * 64) * NCB);
    dst[threadIdx.x] = o;
}

// ---------------------------------------------------------------------------
// Seed pass: exact evaluation of NSEED candidate points per bin, publishing
// tight exact lower bounds into g_best before the screened pass runs.
// grid = 196 blocks x 8 warps; warp w -> (roi w, sub 0). 32 lanes x 8 iters
// cover the 256 channels.
// ---------------------------------------------------------------------------
__global__ void __launch_bounds__(NSEED * 32) k_seed(const float* __restrict__ f,
                                                     const float* __restrict__ rois) {
    int bin  = blockIdx.x;
    int w    = threadIdx.x >> 5;        // roi 0..NSEED-1
    int lane = threadIdx.x & 31;
    int m = bin / MSZ;
    int n = bin - m * MSZ;

    Geom g = make_geom(rois, w, 0, m, n);

    float vmax = -CUDART_INF_F;
#pragma unroll
    for (int ci = 0; ci < CFEAT / 32; ci++) {
        const float* fc = f + (size_t)(ci * 32 + lane) * HWFEAT;
        vmax = fmaxf(vmax, bilin(fc, g));
    }
#pragma unroll
    for (int o = 16; o; o >>= 1)
        vmax = fmaxf(vmax, __shfl_xor_sync(0xffffffffu, vmax, o));
    if (lane == 0) atomicMaxFloat(&g_best[bin], vmax);
}

// ---------------------------------------------------------------------------
// Screened point pass: one warp per (bin, candidate).
// Lanes 0..15 bound the 16 channel blocks via bilinear interp of per-pixel
// block maxes (convex combination => valid upper bound; clamp forces eval).
// Surviving blocks evaluated two-at-a-time across the full warp.
// g_best holds only exact values => pruning is exact & deterministic.
// ---------------------------------------------------------------------------
__global__ void __launch_bounds__(256) k_points(const float* __restrict__ f,
                                                const float* __restrict__ rois) {
    int bin  = blockIdx.x;                          // 0..195
    int cand = blockIdx.y * 8 + (threadIdx.x >> 5); // 0..511
    int lane = threadIdx.x & 31;

    int r = cand >> 2;
    int s = cand & 3;
    int m = bin / MSZ;
    int n = bin - m * MSZ;

    Geom g = make_geom(rois, r, s, m, n);

    float best = __ldg(&g_best[bin]);   // seeded exact lower bound

    bool need = false;
    if (lane < NCB) {
        float m11 = __ldg(&g_Mb[(size_t)g.o11 * NCB + lane]);
        float m12 = __ldg(&g_Mb[(size_t)g.o12 * NCB + lane]);
        float m21 = __ldg(&g_Mb[(size_t)g.o21 * NCB + lane]);
        float m22 = __ldg(&g_Mb[(size_t)g.o22 * NCB + lane]);
        float ub = g.wy_hi * (g.wx_hi * m11 + g.wx_lo * m12) +
                   g.wy_lo * (g.wx_hi * m21 + g.wx_lo * m22);
        need = (!g.wok) || (ub > best);
    }
    unsigned mask = __ballot_sync(0xffffffffu, need);
    if (!mask) return;

    float vmax = -CUDART_INF_F;
    while (mask) {
        int cb0 = __ffs(mask) - 1;
        mask &= mask - 1;
        int cb1 = cb0;
        if (mask) { cb1 = __ffs(mask) - 1; mask &= mask - 1; }
        int cb = (lane < 16) ? cb0 : cb1;
        const float* fc = f + (size_t)(cb * CPB + (lane & 15)) * HWFEAT;
        vmax = fmaxf(vmax, bilin(fc, g));
    }
#pragma unroll
    for (int o = 16; o; o >>= 1)
        vmax = fmaxf(vmax, __shfl_xor_sync(0xffffffffu, vmax, o));
    if (lane == 0) atomicMaxFloat(&g_best[bin], vmax);
}

// ---------------------------------------------------------------------------
// Broadcast g_best[196] to out[R, C, 14, 14] with float4 stores.
// ---------------------------------------------------------------------------
__global__ void __launch_bounds__(256) k_bcast(float4* __restrict__ out, int n4) {
    __shared__ float4 sb[NBIN / 4];
    if (threadIdx.x < NBIN / 4)
        sb[threadIdx.x] = reinterpret_cast<const float4*>(g_best)[threadIdx.x];
    __syncthreads();
    int i = blockIdx.x * 256 + threadIdx.x;
    if (i >= n4) return;
    out[i] = sb[i % (NBIN / 4)];
}

// ---------------------------------------------------------------------------
extern "C" void kernel_launch(void* const* d_in, const int* in_sizes, int n_in,
                              void* d_out, int out_size) {
    const float* feature = (const float*)d_in[0];   // [1,256,200,320] f32
    const float* rois    = (const float*)d_in[1];   // [128,4] f32
    float* out           = (float*)d_out;           // [128,256,14,14] f32

    // Pass 1: per-pixel 16-channel block maxes (+ g_best init)
    k_colmax<<<HW4 / 16, 256>>>((const float4*)feature);

    // Seed: exact per-bin lower bounds from 8 candidates, full parallelism
    k_seed<<<NBIN, NSEED * 32>>>(feature, rois);

    // Screened pass over all (bin, candidate) pairs
    dim3 g2(NBIN, NCAND / 8);
    k_points<<<g2, 256>>>(feature, rois);

    // Broadcast result
    int n4 = out_size / 4;              // 1605632
    k_bcast<<<(n4 + 255) / 256, 256>>>((float4*)out, n4);
}